// round 2
// baseline (speedup 1.0000x reference)
#include <cuda_runtime.h>
#include <cstddef>

#define B 4
#define T 2048
#define C 1024
#define H 64

// scratch for projected q, k, v: [B*T, H] each (2 MB each)
__device__ float g_q[B * T * H];
__device__ float g_k[B * T * H];
__device__ float g_v[B * T * H];

// ---------------------------------------------------------------------------
// Kernel 1: fused QKV projection.  y[row,h] = sum_c x[row,c] * W[h,c]
// grid = (128 row-tiles, 3 weight matrices), block = 256 threads
// Tiles: 64 rows x 64 h-cols, K-chunks of 64. Smem stored k-major so the
// inner loop is 2x LDS.128 + 16 FFMA per k-step.
// ---------------------------------------------------------------------------
#define RT 64
#define KT 64
#define PSTR 68   // smem row stride in floats (pad, multiple of 4)

__global__ __launch_bounds__(256) void qkv_proj(const float* __restrict__ x,
                                                const float* __restrict__ Wq,
                                                const float* __restrict__ Wk,
                                                const float* __restrict__ Wv) {
    __shared__ float xs[KT][PSTR];  // [k][row]
    __shared__ float ws[KT][PSTR];  // [k][h]

    const float* W   = (blockIdx.y == 0) ? Wq : (blockIdx.y == 1) ? Wk : Wv;
    float*       out = (blockIdx.y == 0) ? g_q : (blockIdx.y == 1) ? g_k : g_v;

    const int rowBase = blockIdx.x * RT;
    const int tid = threadIdx.x;
    const int tx = tid & 15;      // h-col group (4 cols each)
    const int ty = tid >> 4;      // row group (4 rows each)

    float acc[4][4] = {};

    for (int k0 = 0; k0 < C; k0 += KT) {
        // Load 64x64 x-tile and 64x64 W-tile, transposing into k-major smem.
        #pragma unroll
        for (int i = 0; i < 4; i++) {
            int f  = tid + i * 256;     // float4 index in tile
            int r  = f >> 4;            // tile row (0..63)
            int c4 = f & 15;            // float4 col (0..15)
            float4 xv = *(const float4*)(x + (size_t)(rowBase + r) * C + k0 + c4 * 4);
            xs[c4 * 4 + 0][r] = xv.x;
            xs[c4 * 4 + 1][r] = xv.y;
            xs[c4 * 4 + 2][r] = xv.z;
            xs[c4 * 4 + 3][r] = xv.w;
            float4 wv = *(const float4*)(W + (size_t)r * C + k0 + c4 * 4);
            ws[c4 * 4 + 0][r] = wv.x;
            ws[c4 * 4 + 1][r] = wv.y;
            ws[c4 * 4 + 2][r] = wv.z;
            ws[c4 * 4 + 3][r] = wv.w;
        }
        __syncthreads();

        #pragma unroll
        for (int kk = 0; kk < KT; kk++) {
            float4 a = *(const float4*)&xs[kk][ty * 4];
            float4 b = *(const float4*)&ws[kk][tx * 4];
            const float av[4] = {a.x, a.y, a.z, a.w};
            const float bv[4] = {b.x, b.y, b.z, b.w};
            #pragma unroll
            for (int i = 0; i < 4; i++)
                #pragma unroll
                for (int j = 0; j < 4; j++)
                    acc[i][j] += av[i] * bv[j];
        }
        __syncthreads();
    }

    #pragma unroll
    for (int i = 0; i < 4; i++) {
        int row = rowBase + ty * 4 + i;
        float4 o = {acc[i][0], acc[i][1], acc[i][2], acc[i][3]};
        *(float4*)(out + (size_t)row * H + tx * 4) = o;
    }
}

// ---------------------------------------------------------------------------
// Kernel 2: causal flash attention over the projected q/k/v.
// grid = (32 pairs, B), block = 256 threads.
// Block handles query tiles {blockIdx.x, 63 - blockIdx.x} (32 queries each)
// so every block runs exactly 65 key tiles -> perfect causal load balance.
// Thread (r = tid>>3, g = tid&7): owns query row r, output cols g*8..g*8+7,
// and S columns {g, g+8, g+16, g+24}.
// ---------------------------------------------------------------------------
#define QT 32
#define KTL 32
// softmax scale 1/sqrt(64) with log2(e) folded in so we can use exp2f
#define QSCALE 0.18033688011112042f   // 0.125 * 1.4426950408889634

__global__ __launch_bounds__(256) void attn(float* __restrict__ out) {
    __shared__ float Qs[QT][PSTR];
    __shared__ float Ks[KTL][PSTR];
    __shared__ float Vs[KTL][PSTR];
    __shared__ float Ps[QT][36];

    const int tid = threadIdx.x;
    const int r = tid >> 3;   // query row in tile
    const int g = tid & 7;    // column group
    const int bT = blockIdx.y * T;

    for (int side = 0; side < 2; side++) {
        const int qt = (side == 0) ? (int)blockIdx.x : (63 - (int)blockIdx.x);
        const int qBase = qt * QT;

        // Load + scale Q tile [32 x 64]
        #pragma unroll
        for (int i = 0; i < 2; i++) {
            int f = tid + i * 256;
            int rr = f >> 4, c4 = f & 15;
            float4 qv = *(const float4*)(g_q + (size_t)(bT + qBase + rr) * H + c4 * 4);
            qv.x *= QSCALE; qv.y *= QSCALE; qv.z *= QSCALE; qv.w *= QSCALE;
            *(float4*)&Qs[rr][c4 * 4] = qv;
        }

        float o0 = 0, o1 = 0, o2 = 0, o3 = 0, o4 = 0, o5 = 0, o6 = 0, o7 = 0;
        float m = -1e30f, l = 0.0f;

        const int nkt = qt + 1;
        for (int j = 0; j < nkt; j++) {
            const int kBase = j * KTL;

            // Load K and V tiles [32 x 64]
            #pragma unroll
            for (int i = 0; i < 2; i++) {
                int f = tid + i * 256;
                int rr = f >> 4, c4 = f & 15;
                size_t base = (size_t)(bT + kBase + rr) * H + c4 * 4;
                *(float4*)&Ks[rr][c4 * 4] = *(const float4*)(g_k + base);
                *(float4*)&Vs[rr][c4 * 4] = *(const float4*)(g_v + base);
            }
            __syncthreads();

            // S = Q K^T : 4 columns per thread
            float s0 = 0, s1 = 0, s2 = 0, s3 = 0;
            #pragma unroll
            for (int h4 = 0; h4 < 16; h4++) {
                float4 qv = *(const float4*)&Qs[r][h4 * 4];
                float4 k0 = *(const float4*)&Ks[g][h4 * 4];
                float4 k1 = *(const float4*)&Ks[g + 8][h4 * 4];
                float4 k2 = *(const float4*)&Ks[g + 16][h4 * 4];
                float4 k3 = *(const float4*)&Ks[g + 24][h4 * 4];
                s0 += qv.x * k0.x + qv.y * k0.y + qv.z * k0.z + qv.w * k0.w;
                s1 += qv.x * k1.x + qv.y * k1.y + qv.z * k1.z + qv.w * k1.w;
                s2 += qv.x * k2.x + qv.y * k2.y + qv.z * k2.z + qv.w * k2.w;
                s3 += qv.x * k3.x + qv.y * k3.y + qv.z * k3.z + qv.w * k3.w;
            }

            // Causal mask (only the diagonal tile needs it; kBase == qBase there)
            if (j == nkt - 1) {
                if (g      > r) s0 = -1e30f;
                if (g + 8  > r) s1 = -1e30f;
                if (g + 16 > r) s2 = -1e30f;
                if (g + 24 > r) s3 = -1e30f;
            }

            // Online softmax (values are already in log2 domain via QSCALE)
            float mx = fmaxf(fmaxf(s0, s1), fmaxf(s2, s3));
            mx = fmaxf(mx, __shfl_xor_sync(0xffffffffu, mx, 1, 8));
            mx = fmaxf(mx, __shfl_xor_sync(0xffffffffu, mx, 2, 8));
            mx = fmaxf(mx, __shfl_xor_sync(0xffffffffu, mx, 4, 8));
            float mnew = fmaxf(m, mx);
            float corr = exp2f(m - mnew);
            float p0 = exp2f(s0 - mnew);
            float p1 = exp2f(s1 - mnew);
            float p2 = exp2f(s2 - mnew);
            float p3 = exp2f(s3 - mnew);
            float rs = p0 + p1 + p2 + p3;
            rs += __shfl_xor_sync(0xffffffffu, rs, 1, 8);
            rs += __shfl_xor_sync(0xffffffffu, rs, 2, 8);
            rs += __shfl_xor_sync(0xffffffffu, rs, 4, 8);
            l = l * corr + rs;
            m = mnew;
            o0 *= corr; o1 *= corr; o2 *= corr; o3 *= corr;
            o4 *= corr; o5 *= corr; o6 *= corr; o7 *= corr;

            Ps[r][g]      = p0;
            Ps[r][g + 8]  = p1;
            Ps[r][g + 16] = p2;
            Ps[r][g + 24] = p3;
            __syncthreads();

            // O += P V : 8 columns per thread
            #pragma unroll
            for (int k4 = 0; k4 < 8; k4++) {
                float4 pv = *(const float4*)&Ps[r][k4 * 4];
                const float pa[4] = {pv.x, pv.y, pv.z, pv.w};
                #pragma unroll
                for (int u = 0; u < 4; u++) {
                    float p = pa[u];
                    int kk = k4 * 4 + u;
                    float4 v0 = *(const float4*)&Vs[kk][g * 8];
                    float4 v1 = *(const float4*)&Vs[kk][g * 8 + 4];
                    o0 += p * v0.x; o1 += p * v0.y; o2 += p * v0.z; o3 += p * v0.w;
                    o4 += p * v1.x; o5 += p * v1.y; o6 += p * v1.z; o7 += p * v1.w;
                }
            }
            __syncthreads();  // protect Ks/Vs/Ps before next iteration's writes
        }

        const float inv = 1.0f / l;
        size_t row = (size_t)(bT + qBase + r);
        float4 w0 = {o0 * inv, o1 * inv, o2 * inv, o3 * inv};
        float4 w1 = {o4 * inv, o5 * inv, o6 * inv, o7 * inv};
        *(float4*)(out + row * H + g * 8)     = w0;
        *(float4*)(out + row * H + g * 8 + 4) = w1;
    }
}

extern "C" void kernel_launch(void* const* d_in, const int* in_sizes, int n_in,
                              void* d_out, int out_size) {
    const float* x  = (const float*)d_in[0];
    const float* Wq = (const float*)d_in[1];
    const float* Wk = (const float*)d_in[2];
    const float* Wv = (const float*)d_in[3];
    float* out = (float*)d_out;

    qkv_proj<<<dim3(B * T / RT, 3), 256>>>(x, Wq, Wk, Wv);
    attn<<<dim3(32, B), 256>>>(out);
}